// round 10
// baseline (speedup 1.0000x reference)
#include <cuda_runtime.h>
#include <cuda_bf16.h>
#include <cstdint>

#define BATCH 64
#define HID   1024
#define TLEN  512
#define NCTA  64
#define NTHR  512
#define NCH1  32   // layer1 K chunks of 64 (K = 1024 h0 + 1024 h1)
#define NCH0  18   // layer0 K chunks of 64 (K = 128 x + 1024 h0)

// Pre-tiled, pre-swizzled operands (gate-permuted rows, SW128, hi/lo split).
__device__ __align__(16) __nv_bfloat16 g_w1[32 * NCH1 * 16384];
__device__ __align__(16) __nv_bfloat16 g_w0[32 * NCH0 * 16384];
__device__ __align__(16) __nv_bfloat16 g_xt[TLEN * 2 * 8192];
__device__ __align__(16) __nv_bfloat16 g_h0t[2][16][8192];
__device__ __align__(16) __nv_bfloat16 g_h1t[2][16][8192];
__device__ float g_biasp[2][4096];
__device__ float g_h1final[BATCH * HID];
__device__ unsigned g_bar_count, g_bar_gen;

__host__ __device__ __forceinline__ uint32_t sw128(uint32_t o) {
    return o ^ ((o >> 3) & 0x70);
}

// smem map: stage A 32KB | stage B 16KB | 3 reduction layers
#define SA        0
#define SB        32768
#define SRED      49152
#define REDSTRIDE 68                       // floats per lane slot (16B aligned)
#define REDLAYER  (4 * 32 * REDSTRIDE * 4) // 34816 bytes
#define SMEM_TOTAL (SRED + 3 * REDLAYER)   // 153600

__device__ __forceinline__ void grid_barrier() {
    __syncthreads();
    if (threadIdx.x == 0) {
        __threadfence();
        unsigned gen = *(volatile unsigned*)&g_bar_gen;
        if (atomicAdd(&g_bar_count, 1u) == NCTA - 1) {
            g_bar_count = 0;
            __threadfence();
            *(volatile unsigned*)&g_bar_gen = gen + 1;
        } else {
            while (*(volatile unsigned*)&g_bar_gen == gen) {}
            __threadfence();
        }
    }
    __syncthreads();
}

#define MMA_BF16(d, a, b)                                                   \
    asm volatile("mma.sync.aligned.m16n8k16.row.col.f32.bf16.bf16.f32 "     \
                 "{%0,%1,%2,%3}, {%4,%5,%6,%7}, {%8,%9}, {%0,%1,%2,%3};"    \
                 : "+f"((d)[0]), "+f"((d)[1]), "+f"((d)[2]), "+f"((d)[3])   \
                 : "r"((a)[0]), "r"((a)[1]), "r"((a)[2]), "r"((a)[3]),      \
                   "r"((b)[0]), "r"((b)[1]))

// One step on one CTA: its 32 hidden dims x 64 batches, full K.
// 16 warps = 4 m-groups (32 gate rows) x 4 K-splits (16 of each 64 chunk).
template <int NCH, bool ISL1>
__device__ __forceinline__ void
run_step(char* smem, int m, int tstep, float* creg)
{
    const int tid  = threadIdx.x;
    const int wid  = tid >> 5, lane = tid & 31;
    const int mg   = wid & 3,  ks   = wid >> 2;
    const int r    = lane >> 2, cq  = lane & 3;

    const __nv_bfloat16* wbase = ISL1 ? (g_w1 + m * NCH1 * 16384)
                                      : (g_w0 + m * NCH0 * 16384);
    auto bsrc_of = [&](int kc) -> const __nv_bfloat16* {
        if (ISL1) return (kc < 16) ? &g_h0t[tstep & 1][kc][0]
                                   : &g_h1t[(tstep + 1) & 1][kc - 16][0];
        else      return (kc < 2)  ? &g_xt[(tstep * 2 + kc) * 8192]
                                   : &g_h0t[(tstep + 1) & 1][kc - 2][0];
    };

    float acc[2][8][4];
#pragma unroll
    for (int d = 0; d < 2; d++)
#pragma unroll
        for (int j = 0; j < 8; j++)
#pragma unroll
            for (int q = 0; q < 4; q++) acc[d][j][q] = 0.0f;

    // Chunk-invariant fragment byte offsets. SW128 on row*128+col2 collapses
    // to row*128 + (col2 ^ ((row&7)<<4)); all our rows have row&7 == r.
    const uint32_t acol = (uint32_t)(((ks * 16 + 2 * cq) * 2) ^ (r << 4));
    const uint32_t a00  = (uint32_t)((mg * 32 + r) * 128) + acol;  // d=0, a0
    const uint32_t b00  = (uint32_t)(r * 128) + acol;              // j=0, b0

    float4 pf[6];
    auto prefetch = [&](int kc) {
        const float4* a4 = reinterpret_cast<const float4*>(wbase + kc * 16384);
        const float4* b4 = reinterpret_cast<const float4*>(bsrc_of(kc));
#pragma unroll
        for (int rr = 0; rr < 4; rr++) pf[rr] = a4[tid + 512 * rr];
        pf[4] = b4[tid]; pf[5] = b4[tid + 512];
    };

    prefetch(0);
    for (int kc = 0; kc < NCH; kc++) {
        __syncthreads();                       // prior chunk fully consumed
        {
            float4* da = reinterpret_cast<float4*>(smem + SA);
            float4* db = reinterpret_cast<float4*>(smem + SB);
#pragma unroll
            for (int rr = 0; rr < 4; rr++) da[tid + 512 * rr] = pf[rr];
            db[tid] = pf[4]; db[tid + 512] = pf[5];
        }
        __syncthreads();
        if (kc + 1 < NCH) prefetch(kc + 1);    // LDG overlaps mma

        uint32_t ah[2][4], al[2][4];
        const char* ph = smem + SA;
        const char* pl = smem + SA + 16384;
#pragma unroll
        for (int d = 0; d < 2; d++) {
            uint32_t o = a00 + d * 2048;
            ah[d][0] = *(const uint32_t*)(ph + o);
            ah[d][1] = *(const uint32_t*)(ph + o + 1024);
            ah[d][2] = *(const uint32_t*)(ph + (o ^ 16));
            ah[d][3] = *(const uint32_t*)(ph + ((o + 1024) ^ 16));
            al[d][0] = *(const uint32_t*)(pl + o);
            al[d][1] = *(const uint32_t*)(pl + o + 1024);
            al[d][2] = *(const uint32_t*)(pl + (o ^ 16));
            al[d][3] = *(const uint32_t*)(pl + ((o + 1024) ^ 16));
        }
        // passes 1+2: (Ahi + Alo) x Bhi, B loaded once per group
#pragma unroll
        for (int g = 0; g < 2; g++) {
            uint32_t bb[4][2];
#pragma unroll
            for (int jj = 0; jj < 4; jj++) {
                uint32_t o = b00 + (g * 4 + jj) * 1024;
                bb[jj][0] = *(const uint32_t*)(smem + SB + o);
                bb[jj][1] = *(const uint32_t*)(smem + SB + (o ^ 16));
            }
#pragma unroll
            for (int jj = 0; jj < 4; jj++) {
                int j = g * 4 + jj;
                MMA_BF16(acc[0][j], ah[0], bb[jj]);
                MMA_BF16(acc[1][j], ah[1], bb[jj]);
                MMA_BF16(acc[0][j], al[0], bb[jj]);
                MMA_BF16(acc[1][j], al[1], bb[jj]);
            }
        }
        // pass 3: Ahi x Blo
#pragma unroll
        for (int g = 0; g < 2; g++) {
            uint32_t bb[4][2];
#pragma unroll
            for (int jj = 0; jj < 4; jj++) {
                uint32_t o = b00 + (g * 4 + jj) * 1024;
                bb[jj][0] = *(const uint32_t*)(smem + SB + 8192 + o);
                bb[jj][1] = *(const uint32_t*)(smem + SB + 8192 + (o ^ 16));
            }
#pragma unroll
            for (int jj = 0; jj < 4; jj++) {
                int j = g * 4 + jj;
                MMA_BF16(acc[0][j], ah[0], bb[jj]);
                MMA_BF16(acc[1][j], ah[1], bb[jj]);
            }
        }
    }

    // ---- cross-K-split reduction: ks 1..3 -> smem, ks 0 sums ----
    __syncthreads();
    if (ks != 0) {
        float4* dst = reinterpret_cast<float4*>(
            smem + SRED + (ks - 1) * REDLAYER + (mg * 32 + lane) * REDSTRIDE * 4);
#pragma unroll
        for (int d = 0; d < 2; d++)
#pragma unroll
            for (int j = 0; j < 8; j++)
                dst[d * 8 + j] = make_float4(acc[d][j][0], acc[d][j][1],
                                             acc[d][j][2], acc[d][j][3]);
    }
    __syncthreads();
    float* trans = reinterpret_cast<float*>(smem);   // 128 rows x 64, stride 68
    if (ks == 0) {
#pragma unroll
        for (int d = 0; d < 2; d++)
#pragma unroll
            for (int j = 0; j < 8; j++) {
                float4 v = make_float4(acc[d][j][0], acc[d][j][1],
                                       acc[d][j][2], acc[d][j][3]);
#pragma unroll
                for (int l = 0; l < 3; l++) {
                    float4 u = reinterpret_cast<const float4*>(
                        smem + SRED + l * REDLAYER +
                        (mg * 32 + lane) * REDSTRIDE * 4)[d * 8 + j];
                    v.x += u.x; v.y += u.y; v.z += u.z; v.w += u.w;
                }
                int row0 = mg * 32 + d * 16 + r;
                int col  = j * 8 + 2 * cq;
                *reinterpret_cast<float2*>(&trans[row0 * 68 + col]) =
                    make_float2(v.x, v.y);
                *reinterpret_cast<float2*>(&trans[(row0 + 8) * 68 + col]) =
                    make_float2(v.z, v.w);
            }
    }
    __syncthreads();

    // ---- cell update: hd = tid>>4 (0..31), batches b0..b0+3 ----
    {
        const int hd = tid >> 4, b0 = (tid & 15) * 4;
        const int hdim = m * 32 + hd;
        const float* bp = g_biasp[ISL1 ? 1 : 0] + m * 128 + hd * 4;
        float4 gi = *reinterpret_cast<const float4*>(&trans[(hd * 4 + 0) * 68 + b0]);
        float4 gf = *reinterpret_cast<const float4*>(&trans[(hd * 4 + 1) * 68 + b0]);
        float4 gg = *reinterpret_cast<const float4*>(&trans[(hd * 4 + 2) * 68 + b0]);
        float4 go = *reinterpret_cast<const float4*>(&trans[(hd * 4 + 3) * 68 + b0]);
        float bi = bp[0], bf = bp[1], bg = bp[2], bo = bp[3];
        float iv[4] = {gi.x, gi.y, gi.z, gi.w};
        float fv[4] = {gf.x, gf.y, gf.z, gf.w};
        float gv[4] = {gg.x, gg.y, gg.z, gg.w};
        float ov[4] = {go.x, go.y, go.z, go.w};
        __nv_bfloat16* hout = ISL1 ? &g_h1t[tstep & 1][0][0] : &g_h0t[tstep & 1][0][0];
        const int kct = hdim >> 6, col = hdim & 63;
#pragma unroll
        for (int q = 0; q < 4; q++) {
            float is = 1.0f / (1.0f + expf(-(iv[q] + bi)));
            float fs = 1.0f / (1.0f + expf(-(fv[q] + bf)));
            float gt = tanhf(gv[q] + bg);
            float os = 1.0f / (1.0f + expf(-(ov[q] + bo)));
            float cn = fs * creg[q] + is * gt;
            creg[q] = cn;
            float h = os * tanhf(cn);
            int b = b0 + q;
            uint32_t off = sw128((uint32_t)(b * 128 + col * 2)) >> 1;
            __nv_bfloat16 hh = __float2bfloat16(h);
            hout[kct * 8192 + off] = hh;
            hout[kct * 8192 + 4096 + off] = __float2bfloat16(h - __bfloat162float(hh));
            if (ISL1 && tstep == TLEN - 1) g_h1final[b * HID + hdim] = h;
        }
    }
}

__global__ void __launch_bounds__(NTHR, 1)
lstm_persistent_kernel()
{
    extern __shared__ __align__(1024) char smem[];
    const int tid = threadIdx.x;

    {   // zero h tile buffers (both parities)
        uint32_t* z0 = reinterpret_cast<uint32_t*>(&g_h0t[0][0][0]);
        uint32_t* z1 = reinterpret_cast<uint32_t*>(&g_h1t[0][0][0]);
        for (int i = blockIdx.x * NTHR + tid; i < 131072; i += NCTA * NTHR) {
            z0[i] = 0u; z1[i] = 0u;
        }
    }
    grid_barrier();

    const bool isl1 = blockIdx.x < 32;
    const int m = isl1 ? blockIdx.x : blockIdx.x - 32;
    float creg[4] = {0.f, 0.f, 0.f, 0.f};

    if (!isl1)
        run_step<NCH0, false>(smem, m, 0, creg);
    grid_barrier();

    for (int t = 0; t < TLEN; t++) {
        if (isl1)
            run_step<NCH1, true>(smem, m, t, creg);
        else if (t + 1 < TLEN)
            run_step<NCH0, false>(smem, m, t + 1, creg);
        grid_barrier();
    }
}

// ---------------- prep kernels (gate-permuted, swizzled, hi/lo split) -------
__device__ __forceinline__ void split_store(__nv_bfloat16* hp, __nv_bfloat16* lp, float w) {
    __nv_bfloat16 hi = __float2bfloat16(w);
    *hp = hi;
    *lp = __float2bfloat16(w - __bfloat162float(hi));
}

__global__ void prep_w1_kernel(const float* __restrict__ Wih1,
                               const float* __restrict__ Whh1) {
    int idx = blockIdx.x * 256 + threadIdx.x;            // 8388608
    int c = idx & 63, r = (idx >> 6) & 127, kc = (idx >> 13) & 31, mm = idx >> 18;
    int orig = (r & 3) * 1024 + mm * 32 + (r >> 2);
    int kg = kc * 64 + c;
    float w = (kg < 1024) ? Wih1[orig * 1024 + kg] : Whh1[orig * 1024 + kg - 1024];
    int base = (mm * NCH1 + kc) * 16384;
    uint32_t off = sw128((uint32_t)(r * 128 + c * 2)) >> 1;
    split_store(&g_w1[base + off], &g_w1[base + 8192 + off], w);
}

__global__ void prep_w0_kernel(const float* __restrict__ Wih0,
                               const float* __restrict__ Whh0) {
    int idx = blockIdx.x * 256 + threadIdx.x;            // 4718592
    int c = idx & 63, r = (idx >> 6) & 127;
    int rest = idx >> 13;
    int kc = rest % NCH0, mm = rest / NCH0;
    int orig = (r & 3) * 1024 + mm * 32 + (r >> 2);
    int kg = kc * 64 + c;
    float w = (kg < 128) ? Wih0[orig * 128 + kg] : Whh0[orig * 1024 + kg - 128];
    int base = (mm * NCH0 + kc) * 16384;
    uint32_t off = sw128((uint32_t)(r * 128 + c * 2)) >> 1;
    split_store(&g_w0[base + off], &g_w0[base + 8192 + off], w);
}

__global__ void prep_x_kernel(const float* __restrict__ x) {
    int idx = blockIdx.x * 256 + threadIdx.x;            // 4194304
    int c = idx & 63, b = (idx >> 6) & 63, kc = (idx >> 12) & 1, t = idx >> 13;
    float v = x[b * (TLEN * 128) + t * 128 + kc * 64 + c];
    int base = (t * 2 + kc) * 8192;
    uint32_t off = sw128((uint32_t)(b * 128 + c * 2)) >> 1;
    split_store(&g_xt[base + off], &g_xt[base + 4096 + off], v);
}

__global__ void prep_bias_kernel(const float* __restrict__ bih0, const float* __restrict__ bhh0,
                                 const float* __restrict__ bih1, const float* __restrict__ bhh1) {
    int idx = blockIdx.x * 256 + threadIdx.x;            // 8192
    int l = idx >> 12, p = idx & 4095;
    int mm = p >> 7, r = p & 127;
    int orig = (r & 3) * 1024 + mm * 32 + (r >> 2);
    g_biasp[l][p] = l ? (bih1[orig] + bhh1[orig]) : (bih0[orig] + bhh0[orig]);
}

__global__ void lstm_fc_kernel(const float* __restrict__ h,
                               const float* __restrict__ w,
                               const float* __restrict__ bias,
                               float* __restrict__ out) {
    __shared__ float warpsum[8];
    int b = blockIdx.x, tid = threadIdx.x;
    float s = 0.0f;
    for (int mm = tid; mm < HID; mm += 256) s += h[b * HID + mm] * w[mm];
#pragma unroll
    for (int o = 16; o; o >>= 1) s += __shfl_down_sync(0xffffffffu, s, o);
    if ((tid & 31) == 0) warpsum[tid >> 5] = s;
    __syncthreads();
    if (tid == 0) {
        float t = 0.0f;
#pragma unroll
        for (int i = 0; i < 8; i++) t += warpsum[i];
        out[b] = t + bias[0];
    }
}

__global__ void ncu_marker_a() {}

extern "C" void kernel_launch(void* const* d_in, const int* in_sizes, int n_in,
                              void* d_out, int out_size) {
    const float* x    = (const float*)d_in[0];
    const float* Wih0 = (const float*)d_in[1];
    const float* Whh0 = (const float*)d_in[2];
    const float* bih0 = (const float*)d_in[3];
    const float* bhh0 = (const float*)d_in[4];
    const float* Wih1 = (const float*)d_in[5];
    const float* Whh1 = (const float*)d_in[6];
    const float* bih1 = (const float*)d_in[7];
    const float* bhh1 = (const float*)d_in[8];
    const float* fcw  = (const float*)d_in[9];
    const float* fcb  = (const float*)d_in[10];
    float* out = (float*)d_out;

    cudaFuncSetAttribute(lstm_persistent_kernel,
                         cudaFuncAttributeMaxDynamicSharedMemorySize, SMEM_TOTAL);
    float* h1f;
    cudaGetSymbolAddress((void**)&h1f, g_h1final);

    prep_w1_kernel<<<32768, 256>>>(Wih1, Whh1);
    prep_w0_kernel<<<18432, 256>>>(Wih0, Whh0);
    prep_x_kernel<<<16384, 256>>>(x);
    prep_bias_kernel<<<32, 256>>>(bih0, bhh0, bih1, bhh1);
    ncu_marker_a<<<1, 32>>>();                 // persistent = launch idx 5
    lstm_persistent_kernel<<<NCTA, NTHR, SMEM_TOTAL>>>();
    lstm_fc_kernel<<<64, 256>>>(h1f, fcw, fcb, out);
}

// round 11
// speedup vs baseline: 1.9374x; 1.9374x over previous
#include <cuda_runtime.h>
#include <cuda_bf16.h>
#include <cstdint>

#define BATCH 64
#define HID   1024
#define TLEN  512
#define NCTA  64
#define NTHR  512
#define NCH1  32   // layer1 K chunks of 64 (K = 1024 h0 + 1024 h1)
#define NCH0  18   // layer0 K chunks of 64 (K = 128 x + 1024 h0)

// Pre-tiled, pre-swizzled operands (gate-permuted rows, SW128, hi/lo split).
__device__ __align__(16) __nv_bfloat16 g_w1[32 * NCH1 * 16384];
__device__ __align__(16) __nv_bfloat16 g_w0[32 * NCH0 * 16384];
__device__ __align__(16) __nv_bfloat16 g_xt[TLEN * 2 * 8192];
__device__ __align__(16) __nv_bfloat16 g_h0t[2][16][8192];
__device__ __align__(16) __nv_bfloat16 g_h1t[2][16][8192];
__device__ float g_biasp[2][4096];
__device__ float g_h1final[BATCH * HID];
__device__ unsigned g_bar_count, g_bar_gen;

__host__ __device__ __forceinline__ uint32_t sw128(uint32_t o) {
    return o ^ ((o >> 3) & 0x70);
}

// smem map: 2 staging slots (A 32KB + B 16KB each) + 3 reduction layers.
// trans buffer reuses slot 0 after the last chunk is consumed.
#define SLOT(s)   ((s) * 49152)
#define SRED      98304
#define REDSTRIDE 68
#define REDLAYER  (4 * 32 * REDSTRIDE * 4)      // 34816 B
#define SMEM_TOTAL (SRED + 3 * REDLAYER)        // 202752 B

__device__ __forceinline__ uint32_t smem_u32(const void* p) {
    uint32_t a;
    asm("{ .reg .u64 t; cvta.to.shared.u64 t, %1; cvt.u32.u64 %0, t; }" : "=r"(a) : "l"(p));
    return a;
}
#define CP_ASYNC16(dst_u32, src_ptr) \
    asm volatile("cp.async.cg.shared.global [%0], [%1], 16;" \
                 :: "r"(dst_u32), "l"(src_ptr) : "memory")
#define CP_COMMIT() asm volatile("cp.async.commit_group;" ::: "memory")
#define CP_WAIT1()  asm volatile("cp.async.wait_group 1;" ::: "memory")
#define CP_WAIT0()  asm volatile("cp.async.wait_group 0;" ::: "memory")

__device__ __forceinline__ void grid_barrier() {
    __syncthreads();
    if (threadIdx.x == 0) {
        __threadfence();
        unsigned gen = *(volatile unsigned*)&g_bar_gen;
        if (atomicAdd(&g_bar_count, 1u) == NCTA - 1) {
            g_bar_count = 0;
            __threadfence();
            *(volatile unsigned*)&g_bar_gen = gen + 1;
        } else {
            while (*(volatile unsigned*)&g_bar_gen == gen) {}
            __threadfence();
        }
    }
    __syncthreads();
}

#define MMA_BF16(d, a, b)                                                   \
    asm volatile("mma.sync.aligned.m16n8k16.row.col.f32.bf16.bf16.f32 "     \
                 "{%0,%1,%2,%3}, {%4,%5,%6,%7}, {%8,%9}, {%0,%1,%2,%3};"    \
                 : "+f"((d)[0]), "+f"((d)[1]), "+f"((d)[2]), "+f"((d)[3])   \
                 : "r"((a)[0]), "r"((a)[1]), "r"((a)[2]), "r"((a)[3]),      \
                   "r"((b)[0]), "r"((b)[1]))

// One step on one CTA: its 32 hidden dims x 64 batches, full K.
// 16 warps = 4 m-groups (32 gate rows) x 4 K-splits (16 of each 64 chunk).
template <int NCH, bool ISL1>
__device__ __forceinline__ void
run_step(char* smem, uint32_t sbase, int m, int tstep, float* creg)
{
    const int tid  = threadIdx.x;
    const int wid  = tid >> 5, lane = tid & 31;
    const int mg   = wid & 3,  ks   = wid >> 2;
    const int r    = lane >> 2, cq  = lane & 3;

    const __nv_bfloat16* wbase = ISL1 ? (g_w1 + m * NCH1 * 16384)
                                      : (g_w0 + m * NCH0 * 16384);
    auto bsrc_of = [&](int kc) -> const __nv_bfloat16* {
        if (ISL1) return (kc < 16) ? &g_h0t[tstep & 1][kc][0]
                                   : &g_h1t[(tstep + 1) & 1][kc - 16][0];
        else      return (kc < 2)  ? &g_xt[(tstep * 2 + kc) * 8192]
                                   : &g_h0t[(tstep + 1) & 1][kc - 2][0];
    };

    // async staging: A 32KB (4x16B/thread) + B 16KB (2x16B/thread) per chunk
    auto issue = [&](int kc) {
        const int s = kc & 1;
        const char* ga = reinterpret_cast<const char*>(wbase + kc * 16384);
        const char* gb = reinterpret_cast<const char*>(bsrc_of(kc));
        uint32_t da = sbase + SLOT(s);
        uint32_t db = da + 32768;
#pragma unroll
        for (int rr = 0; rr < 4; rr++)
            CP_ASYNC16(da + (tid + 512 * rr) * 16, ga + (tid + 512 * rr) * 16);
        CP_ASYNC16(db + tid * 16, gb + tid * 16);
        CP_ASYNC16(db + (tid + 512) * 16, gb + (tid + 512) * 16);
        CP_COMMIT();
    };

    float acc[2][8][4];
#pragma unroll
    for (int d = 0; d < 2; d++)
#pragma unroll
        for (int j = 0; j < 8; j++)
#pragma unroll
            for (int q = 0; q < 4; q++) acc[d][j][q] = 0.0f;

    // Chunk-invariant fragment byte offsets (validated R10, rel_err 6.8e-6).
    const uint32_t acol = (uint32_t)(((ks * 16 + 2 * cq) * 2) ^ (r << 4));
    const uint32_t a00  = (uint32_t)((mg * 32 + r) * 128) + acol;
    const uint32_t b00  = (uint32_t)(r * 128) + acol;

    issue(0);
    for (int kc = 0; kc < NCH; kc++) {
        if (kc + 1 < NCH) { issue(kc + 1); CP_WAIT1(); }
        else              { CP_WAIT0(); }
        __syncthreads();                       // slot kc&1 full for all warps

        const char* ph = smem + SLOT(kc & 1);
        const char* pl = ph + 16384;
        const char* pb = ph + 32768;

        uint32_t ah[2][4], al[2][4];
#pragma unroll
        for (int d = 0; d < 2; d++) {
            uint32_t o = a00 + d * 2048;
            ah[d][0] = *(const uint32_t*)(ph + o);
            ah[d][1] = *(const uint32_t*)(ph + o + 1024);
            ah[d][2] = *(const uint32_t*)(ph + (o ^ 16));
            ah[d][3] = *(const uint32_t*)(ph + ((o + 1024) ^ 16));
            al[d][0] = *(const uint32_t*)(pl + o);
            al[d][1] = *(const uint32_t*)(pl + o + 1024);
            al[d][2] = *(const uint32_t*)(pl + (o ^ 16));
            al[d][3] = *(const uint32_t*)(pl + ((o + 1024) ^ 16));
        }
        // passes 1+2: (Ahi + Alo) x Bhi
#pragma unroll
        for (int g = 0; g < 2; g++) {
            uint32_t bb[4][2];
#pragma unroll
            for (int jj = 0; jj < 4; jj++) {
                uint32_t o = b00 + (g * 4 + jj) * 1024;
                bb[jj][0] = *(const uint32_t*)(pb + o);
                bb[jj][1] = *(const uint32_t*)(pb + (o ^ 16));
            }
#pragma unroll
            for (int jj = 0; jj < 4; jj++) {
                int j = g * 4 + jj;
                MMA_BF16(acc[0][j], ah[0], bb[jj]);
                MMA_BF16(acc[1][j], ah[1], bb[jj]);
                MMA_BF16(acc[0][j], al[0], bb[jj]);
                MMA_BF16(acc[1][j], al[1], bb[jj]);
            }
        }
        // pass 3: Ahi x Blo
#pragma unroll
        for (int g = 0; g < 2; g++) {
            uint32_t bb[4][2];
#pragma unroll
            for (int jj = 0; jj < 4; jj++) {
                uint32_t o = b00 + (g * 4 + jj) * 1024;
                bb[jj][0] = *(const uint32_t*)(pb + 8192 + o);
                bb[jj][1] = *(const uint32_t*)(pb + 8192 + (o ^ 16));
            }
#pragma unroll
            for (int jj = 0; jj < 4; jj++) {
                int j = g * 4 + jj;
                MMA_BF16(acc[0][j], ah[0], bb[jj]);
                MMA_BF16(acc[1][j], ah[1], bb[jj]);
            }
        }
        __syncthreads();                       // slot reusable by issue(kc+2)
    }

    // ---- cross-K-split reduction: ks 1..3 -> smem, ks 0 sums ----
    if (ks != 0) {
        float4* dst = reinterpret_cast<float4*>(
            smem + SRED + (ks - 1) * REDLAYER + (mg * 32 + lane) * REDSTRIDE * 4);
#pragma unroll
        for (int d = 0; d < 2; d++)
#pragma unroll
            for (int j = 0; j < 8; j++)
                dst[d * 8 + j] = make_float4(acc[d][j][0], acc[d][j][1],
                                             acc[d][j][2], acc[d][j][3]);
    }
    __syncthreads();
    float* trans = reinterpret_cast<float*>(smem);   // 128 rows x 64, stride 68
    if (ks == 0) {
#pragma unroll
        for (int d = 0; d < 2; d++)
#pragma unroll
            for (int j = 0; j < 8; j++) {
                float4 v = make_float4(acc[d][j][0], acc[d][j][1],
                                       acc[d][j][2], acc[d][j][3]);
#pragma unroll
                for (int l = 0; l < 3; l++) {
                    float4 u = reinterpret_cast<const float4*>(
                        smem + SRED + l * REDLAYER +
                        (mg * 32 + lane) * REDSTRIDE * 4)[d * 8 + j];
                    v.x += u.x; v.y += u.y; v.z += u.z; v.w += u.w;
                }
                int row0 = mg * 32 + d * 16 + r;
                int col  = j * 8 + 2 * cq;
                *reinterpret_cast<float2*>(&trans[row0 * 68 + col]) =
                    make_float2(v.x, v.y);
                *reinterpret_cast<float2*>(&trans[(row0 + 8) * 68 + col]) =
                    make_float2(v.z, v.w);
            }
    }
    __syncthreads();

    // ---- cell update: hd = tid>>4 (0..31), batches b0..b0+3 ----
    {
        const int hd = tid >> 4, b0 = (tid & 15) * 4;
        const int hdim = m * 32 + hd;
        const float* bp = g_biasp[ISL1 ? 1 : 0] + m * 128 + hd * 4;
        float4 gi = *reinterpret_cast<const float4*>(&trans[(hd * 4 + 0) * 68 + b0]);
        float4 gf = *reinterpret_cast<const float4*>(&trans[(hd * 4 + 1) * 68 + b0]);
        float4 gg = *reinterpret_cast<const float4*>(&trans[(hd * 4 + 2) * 68 + b0]);
        float4 go = *reinterpret_cast<const float4*>(&trans[(hd * 4 + 3) * 68 + b0]);
        float bi = bp[0], bf = bp[1], bg = bp[2], bo = bp[3];
        float iv[4] = {gi.x, gi.y, gi.z, gi.w};
        float fv[4] = {gf.x, gf.y, gf.z, gf.w};
        float gv[4] = {gg.x, gg.y, gg.z, gg.w};
        float ov[4] = {go.x, go.y, go.z, go.w};
        __nv_bfloat16* hout = ISL1 ? &g_h1t[tstep & 1][0][0] : &g_h0t[tstep & 1][0][0];
        const int kct = hdim >> 6, col = hdim & 63;
#pragma unroll
        for (int q = 0; q < 4; q++) {
            float is = 1.0f / (1.0f + expf(-(iv[q] + bi)));
            float fs = 1.0f / (1.0f + expf(-(fv[q] + bf)));
            float gt = tanhf(gv[q] + bg);
            float os = 1.0f / (1.0f + expf(-(ov[q] + bo)));
            float cn = fs * creg[q] + is * gt;
            creg[q] = cn;
            float h = os * tanhf(cn);
            int b = b0 + q;
            uint32_t off = sw128((uint32_t)(b * 128 + col * 2)) >> 1;
            __nv_bfloat16 hh = __float2bfloat16(h);
            hout[kct * 8192 + off] = hh;
            hout[kct * 8192 + 4096 + off] = __float2bfloat16(h - __bfloat162float(hh));
            if (ISL1 && tstep == TLEN - 1) g_h1final[b * HID + hdim] = h;
        }
    }
}

__global__ void __launch_bounds__(NTHR, 1)
lstm_persistent_kernel()
{
    extern __shared__ __align__(1024) char smem[];
    uint32_t sbase = smem_u32(smem);
    const int tid = threadIdx.x;

    {   // zero h tile buffers (both parities)
        uint32_t* z0 = reinterpret_cast<uint32_t*>(&g_h0t[0][0][0]);
        uint32_t* z1 = reinterpret_cast<uint32_t*>(&g_h1t[0][0][0]);
        for (int i = blockIdx.x * NTHR + tid; i < 131072; i += NCTA * NTHR) {
            z0[i] = 0u; z1[i] = 0u;
        }
    }
    grid_barrier();

    const bool isl1 = blockIdx.x < 32;
    const int m = isl1 ? blockIdx.x : blockIdx.x - 32;
    float creg[4] = {0.f, 0.f, 0.f, 0.f};

    if (!isl1)
        run_step<NCH0, false>(smem, sbase, m, 0, creg);
    grid_barrier();

    for (int t = 0; t < TLEN; t++) {
        if (isl1)
            run_step<NCH1, true>(smem, sbase, m, t, creg);
        else if (t + 1 < TLEN)
            run_step<NCH0, false>(smem, sbase, m, t + 1, creg);
        grid_barrier();
    }
}

// ---------------- prep kernels (gate-permuted, swizzled, hi/lo split) -------
__device__ __forceinline__ void split_store(__nv_bfloat16* hp, __nv_bfloat16* lp, float w) {
    __nv_bfloat16 hi = __float2bfloat16(w);
    *hp = hi;
    *lp = __float2bfloat16(w - __bfloat162float(hi));
}

// combined W prep: blocks [0, 32768) -> W1, [32768, 51200) -> W0
__global__ void prep_w_kernel(const float* __restrict__ Wih1, const float* __restrict__ Whh1,
                              const float* __restrict__ Wih0, const float* __restrict__ Whh0) {
    if (blockIdx.x < 32768) {
        int idx = blockIdx.x * 256 + threadIdx.x;
        int c = idx & 63, r = (idx >> 6) & 127, kc = (idx >> 13) & 31, mm = idx >> 18;
        int orig = (r & 3) * 1024 + mm * 32 + (r >> 2);
        int kg = kc * 64 + c;
        float w = (kg < 1024) ? Wih1[orig * 1024 + kg] : Whh1[orig * 1024 + kg - 1024];
        int base = (mm * NCH1 + kc) * 16384;
        uint32_t off = sw128((uint32_t)(r * 128 + c * 2)) >> 1;
        split_store(&g_w1[base + off], &g_w1[base + 8192 + off], w);
    } else {
        int idx = (blockIdx.x - 32768) * 256 + threadIdx.x;
        int c = idx & 63, r = (idx >> 6) & 127;
        int rest = idx >> 13;
        int kc = rest % NCH0, mm = rest / NCH0;
        int orig = (r & 3) * 1024 + mm * 32 + (r >> 2);
        int kg = kc * 64 + c;
        float w = (kg < 128) ? Wih0[orig * 128 + kg] : Whh0[orig * 1024 + kg - 128];
        int base = (mm * NCH0 + kc) * 16384;
        uint32_t off = sw128((uint32_t)(r * 128 + c * 2)) >> 1;
        split_store(&g_w0[base + off], &g_w0[base + 8192 + off], w);
    }
}

__global__ void prep_x_kernel(const float* __restrict__ x) {
    int idx = blockIdx.x * 256 + threadIdx.x;            // 4194304
    int c = idx & 63, b = (idx >> 6) & 63, kc = (idx >> 12) & 1, t = idx >> 13;
    float v = x[b * (TLEN * 128) + t * 128 + kc * 64 + c];
    int base = (t * 2 + kc) * 8192;
    uint32_t off = sw128((uint32_t)(b * 128 + c * 2)) >> 1;
    split_store(&g_xt[base + off], &g_xt[base + 4096 + off], v);
}

__global__ void prep_bias_kernel(const float* __restrict__ bih0, const float* __restrict__ bhh0,
                                 const float* __restrict__ bih1, const float* __restrict__ bhh1) {
    int idx = blockIdx.x * 256 + threadIdx.x;            // 8192
    int l = idx >> 12, p = idx & 4095;
    int mm = p >> 7, r = p & 127;
    int orig = (r & 3) * 1024 + mm * 32 + (r >> 2);
    g_biasp[l][p] = l ? (bih1[orig] + bhh1[orig]) : (bih0[orig] + bhh0[orig]);
}

__global__ void lstm_fc_kernel(const float* __restrict__ h,
                               const float* __restrict__ w,
                               const float* __restrict__ bias,
                               float* __restrict__ out) {
    __shared__ float warpsum[8];
    int b = blockIdx.x, tid = threadIdx.x;
    float s = 0.0f;
    for (int mm = tid; mm < HID; mm += 256) s += h[b * HID + mm] * w[mm];
#pragma unroll
    for (int o = 16; o; o >>= 1) s += __shfl_down_sync(0xffffffffu, s, o);
    if ((tid & 31) == 0) warpsum[tid >> 5] = s;
    __syncthreads();
    if (tid == 0) {
        float t = 0.0f;
#pragma unroll
        for (int i = 0; i < 8; i++) t += warpsum[i];
        out[b] = t + bias[0];
    }
}

extern "C" void kernel_launch(void* const* d_in, const int* in_sizes, int n_in,
                              void* d_out, int out_size) {
    const float* x    = (const float*)d_in[0];
    const float* Wih0 = (const float*)d_in[1];
    const float* Whh0 = (const float*)d_in[2];
    const float* bih0 = (const float*)d_in[3];
    const float* bhh0 = (const float*)d_in[4];
    const float* Wih1 = (const float*)d_in[5];
    const float* Whh1 = (const float*)d_in[6];
    const float* bih1 = (const float*)d_in[7];
    const float* bhh1 = (const float*)d_in[8];
    const float* fcw  = (const float*)d_in[9];
    const float* fcb  = (const float*)d_in[10];
    float* out = (float*)d_out;

    cudaFuncSetAttribute(lstm_persistent_kernel,
                         cudaFuncAttributeMaxDynamicSharedMemorySize, SMEM_TOTAL);
    float* h1f;
    cudaGetSymbolAddress((void**)&h1f, g_h1final);

    // persistent kernel deliberately placed as the 4th launch (ncu capture slot)
    prep_bias_kernel<<<32, 256>>>(bih0, bhh0, bih1, bhh1);
    prep_w_kernel<<<51200, 256>>>(Wih1, Whh1, Wih0, Whh0);
    prep_x_kernel<<<16384, 256>>>(x);
    lstm_persistent_kernel<<<NCTA, NTHR, SMEM_TOTAL>>>();
    lstm_fc_kernel<<<64, 256>>>(h1f, fcw, fcb, out);
}

// round 12
// speedup vs baseline: 3.2702x; 1.6879x over previous
#include <cuda_runtime.h>
#include <cuda_bf16.h>
#include <cstdint>

#define BATCH 64
#define HID   1024
#define TLEN  512
#define NCTA  128
#define NTHR  256
#define NCH1  32   // layer1 K chunks of 64 (K = 1024 h0 + 1024 h1)
#define NCH0  18   // layer0 K chunks of 64 (K = 128 x + 1024 h0)

// Pre-tiled, pre-swizzled operands (gate-permuted rows, SW128, hi/lo split).
__device__ __align__(16) __nv_bfloat16 g_w1[32 * NCH1 * 16384];
__device__ __align__(16) __nv_bfloat16 g_w0[32 * NCH0 * 16384];
__device__ __align__(16) __nv_bfloat16 g_xt[TLEN * 2 * 8192];
__device__ __align__(16) __nv_bfloat16 g_h0t[2][16][8192];
__device__ __align__(16) __nv_bfloat16 g_h1t[2][16][8192];
__device__ float g_biasp[2][4096];
__device__ float g_h1final[BATCH * HID];
__device__ unsigned g_bar_count, g_bar_gen;

__host__ __device__ __forceinline__ uint32_t sw128(uint32_t o) {
    return o ^ ((o >> 3) & 0x70);
}

// smem map: 2 staging slots (A 16KB + B 16KB each) + 3 reduction layers.
// trans buffer (64 x 68 floats = 17408 B) reuses slot 0 after last chunk.
#define SLOT(s)   ((s) * 32768)
#define SRED      65536
#define REDSTRIDE 68
#define REDLAYER  (2 * 32 * REDSTRIDE * 4)      // 17408 B
#define SMEM_TOTAL (SRED + 3 * REDLAYER)        // 117760 B

__device__ __forceinline__ uint32_t smem_u32(const void* p) {
    uint32_t a;
    asm("{ .reg .u64 t; cvta.to.shared.u64 t, %1; cvt.u32.u64 %0, t; }" : "=r"(a) : "l"(p));
    return a;
}
#define CP_ASYNC16(dst_u32, src_ptr) \
    asm volatile("cp.async.cg.shared.global [%0], [%1], 16;" \
                 :: "r"(dst_u32), "l"(src_ptr) : "memory")
#define CP_COMMIT() asm volatile("cp.async.commit_group;" ::: "memory")
#define CP_WAIT1()  asm volatile("cp.async.wait_group 1;" ::: "memory")
#define CP_WAIT0()  asm volatile("cp.async.wait_group 0;" ::: "memory")

__device__ __forceinline__ void grid_barrier() {
    __syncthreads();
    if (threadIdx.x == 0) {
        __threadfence();
        unsigned gen = *(volatile unsigned*)&g_bar_gen;
        if (atomicAdd(&g_bar_count, 1u) == NCTA - 1) {
            g_bar_count = 0;
            __threadfence();
            *(volatile unsigned*)&g_bar_gen = gen + 1;
        } else {
            while (*(volatile unsigned*)&g_bar_gen == gen) {}
            __threadfence();
        }
    }
    __syncthreads();
}

#define MMA_BF16(d, a, b)                                                   \
    asm volatile("mma.sync.aligned.m16n8k16.row.col.f32.bf16.bf16.f32 "     \
                 "{%0,%1,%2,%3}, {%4,%5,%6,%7}, {%8,%9}, {%0,%1,%2,%3};"    \
                 : "+f"((d)[0]), "+f"((d)[1]), "+f"((d)[2]), "+f"((d)[3])   \
                 : "r"((a)[0]), "r"((a)[1]), "r"((a)[2]), "r"((a)[3]),      \
                   "r"((b)[0]), "r"((b)[1]))

// One step, one CTA: 64 gate rows (= 16 hidden dims) x 64 batches, full K.
// 8 warps = 2 m-groups (32 gate rows) x 4 K-splits (16 of each 64 chunk).
// mt = tile index 0..63: m = mt>>1 (128-row weight tile), half = mt&1.
template <int NCH, bool ISL1>
__device__ __forceinline__ void
run_step(char* smem, uint32_t sbase, int mt, int tstep, float* creg)
{
    const int tid  = threadIdx.x;
    const int wid  = tid >> 5, lane = tid & 31;
    const int mg   = wid & 1,  ks   = wid >> 1;
    const int r    = lane >> 2, cq  = lane & 3;
    const int m    = mt >> 1,  half = mt & 1;

    const __nv_bfloat16* wtile = ISL1 ? (g_w1 + m * NCH1 * 16384)
                                      : (g_w0 + m * NCH0 * 16384);
    auto bsrc_of = [&](int kc) -> const __nv_bfloat16* {
        if (ISL1) return (kc < 16) ? &g_h0t[tstep & 1][kc][0]
                                   : &g_h1t[(tstep + 1) & 1][kc - 16][0];
        else      return (kc < 2)  ? &g_xt[(tstep * 2 + kc) * 8192]
                                   : &g_h0t[(tstep + 1) & 1][kc - 2][0];
    };

    // async staging per chunk: A 16KB (hi 8KB + lo 8KB of our 64 rows) + B 16KB
    auto issue = [&](int kc) {
        const int s = kc & 1;
        // element offsets: hi rows at half*4096, lo region starts at +8192 elems
        const char* ga_hi = reinterpret_cast<const char*>(
            wtile + kc * 16384 + half * 4096);
        const char* ga_lo = ga_hi + 16384;     // +8192 elements
        const char* gb = reinterpret_cast<const char*>(bsrc_of(kc));
        uint32_t da = sbase + SLOT(s);
        uint32_t db = da + 16384;
#pragma unroll
        for (int rr = 0; rr < 2; rr++) {
            CP_ASYNC16(da + (tid + 256 * rr) * 16, ga_hi + (tid + 256 * rr) * 16);
            CP_ASYNC16(da + 8192 + (tid + 256 * rr) * 16, ga_lo + (tid + 256 * rr) * 16);
            CP_ASYNC16(db + (tid + 256 * rr) * 16, gb + (tid + 256 * rr) * 16);
            CP_ASYNC16(db + 8192 + (tid + 256 * rr) * 16, gb + 8192 + (tid + 256 * rr) * 16);
        }
        CP_COMMIT();
    };

    float acc[2][8][4];
#pragma unroll
    for (int d = 0; d < 2; d++)
#pragma unroll
        for (int j = 0; j < 8; j++)
#pragma unroll
            for (int q = 0; q < 4; q++) acc[d][j][q] = 0.0f;

    // Chunk-invariant fragment byte offsets (math validated R10/R11).
    const uint32_t acol = (uint32_t)(((ks * 16 + 2 * cq) * 2) ^ (r << 4));
    const uint32_t a00  = (uint32_t)((mg * 32 + r) * 128) + acol;  // < 8192
    const uint32_t b00  = (uint32_t)(r * 128) + acol;

    issue(0);
    for (int kc = 0; kc < NCH; kc++) {
        if (kc + 1 < NCH) { issue(kc + 1); CP_WAIT1(); }
        else              { CP_WAIT0(); }
        __syncthreads();                       // slot kc&1 full for all warps

        const char* ph = smem + SLOT(kc & 1);  // A hi (64 x 128B)
        const char* pl = ph + 8192;            // A lo
        const char* pb = ph + 16384;           // B hi; B lo at +8192

        uint32_t ah[2][4], al[2][4];
#pragma unroll
        for (int d = 0; d < 2; d++) {
            uint32_t o = a00 + d * 2048;
            ah[d][0] = *(const uint32_t*)(ph + o);
            ah[d][1] = *(const uint32_t*)(ph + o + 1024);
            ah[d][2] = *(const uint32_t*)(ph + (o ^ 16));
            ah[d][3] = *(const uint32_t*)(ph + ((o + 1024) ^ 16));
            al[d][0] = *(const uint32_t*)(pl + o);
            al[d][1] = *(const uint32_t*)(pl + o + 1024);
            al[d][2] = *(const uint32_t*)(pl + (o ^ 16));
            al[d][3] = *(const uint32_t*)(pl + ((o + 1024) ^ 16));
        }
        // passes 1+2: (Ahi + Alo) x Bhi
#pragma unroll
        for (int g = 0; g < 2; g++) {
            uint32_t bb[4][2];
#pragma unroll
            for (int jj = 0; jj < 4; jj++) {
                uint32_t o = b00 + (g * 4 + jj) * 1024;
                bb[jj][0] = *(const uint32_t*)(pb + o);
                bb[jj][1] = *(const uint32_t*)(pb + (o ^ 16));
            }
#pragma unroll
            for (int jj = 0; jj < 4; jj++) {
                int j = g * 4 + jj;
                MMA_BF16(acc[0][j], ah[0], bb[jj]);
                MMA_BF16(acc[1][j], ah[1], bb[jj]);
                MMA_BF16(acc[0][j], al[0], bb[jj]);
                MMA_BF16(acc[1][j], al[1], bb[jj]);
            }
        }
        // pass 3: Ahi x Blo
#pragma unroll
        for (int g = 0; g < 2; g++) {
            uint32_t bb[4][2];
#pragma unroll
            for (int jj = 0; jj < 4; jj++) {
                uint32_t o = b00 + (g * 4 + jj) * 1024;
                bb[jj][0] = *(const uint32_t*)(pb + 8192 + o);
                bb[jj][1] = *(const uint32_t*)(pb + 8192 + (o ^ 16));
            }
#pragma unroll
            for (int jj = 0; jj < 4; jj++) {
                int j = g * 4 + jj;
                MMA_BF16(acc[0][j], ah[0], bb[jj]);
                MMA_BF16(acc[1][j], ah[1], bb[jj]);
            }
        }
        __syncthreads();                       // slot reusable by issue(kc+2)
    }

    // ---- cross-K-split reduction: ks 1..3 -> smem, ks 0 sums ----
    if (ks != 0) {
        float4* dst = reinterpret_cast<float4*>(
            smem + SRED + (ks - 1) * REDLAYER + (mg * 32 + lane) * REDSTRIDE * 4);
#pragma unroll
        for (int d = 0; d < 2; d++)
#pragma unroll
            for (int j = 0; j < 8; j++)
                dst[d * 8 + j] = make_float4(acc[d][j][0], acc[d][j][1],
                                             acc[d][j][2], acc[d][j][3]);
    }
    __syncthreads();
    float* trans = reinterpret_cast<float*>(smem);   // 64 rows x 64, stride 68
    if (ks == 0) {
#pragma unroll
        for (int d = 0; d < 2; d++)
#pragma unroll
            for (int j = 0; j < 8; j++) {
                float4 v = make_float4(acc[d][j][0], acc[d][j][1],
                                       acc[d][j][2], acc[d][j][3]);
#pragma unroll
                for (int l = 0; l < 3; l++) {
                    float4 u = reinterpret_cast<const float4*>(
                        smem + SRED + l * REDLAYER +
                        (mg * 32 + lane) * REDSTRIDE * 4)[d * 8 + j];
                    v.x += u.x; v.y += u.y; v.z += u.z; v.w += u.w;
                }
                int row0 = mg * 32 + d * 16 + r;
                int col  = j * 8 + 2 * cq;
                *reinterpret_cast<float2*>(&trans[row0 * 68 + col]) =
                    make_float2(v.x, v.y);
                *reinterpret_cast<float2*>(&trans[(row0 + 8) * 68 + col]) =
                    make_float2(v.z, v.w);
            }
    }
    __syncthreads();

    // ---- cell update: 1024 cells (16 hd x 64 b), 4 per thread ----
    {
        const int hd = tid >> 4, b0 = (tid & 15) * 4;          // hd 0..15
        const int hdim = mt * 16 + hd;                          // global hidden dim
        const float* bp = g_biasp[ISL1 ? 1 : 0] + m * 128 + half * 64 + hd * 4;
        float4 gi = *reinterpret_cast<const float4*>(&trans[(hd * 4 + 0) * 68 + b0]);
        float4 gf = *reinterpret_cast<const float4*>(&trans[(hd * 4 + 1) * 68 + b0]);
        float4 gg = *reinterpret_cast<const float4*>(&trans[(hd * 4 + 2) * 68 + b0]);
        float4 go = *reinterpret_cast<const float4*>(&trans[(hd * 4 + 3) * 68 + b0]);
        float bi = bp[0], bf = bp[1], bg = bp[2], bo = bp[3];
        float iv[4] = {gi.x, gi.y, gi.z, gi.w};
        float fv[4] = {gf.x, gf.y, gf.z, gf.w};
        float gv[4] = {gg.x, gg.y, gg.z, gg.w};
        float ov[4] = {go.x, go.y, go.z, go.w};
        __nv_bfloat16* hout = ISL1 ? &g_h1t[tstep & 1][0][0] : &g_h0t[tstep & 1][0][0];
        const int kct = hdim >> 6, col = hdim & 63;
#pragma unroll
        for (int q = 0; q < 4; q++) {
            float is = 1.0f / (1.0f + expf(-(iv[q] + bi)));
            float fs = 1.0f / (1.0f + expf(-(fv[q] + bf)));
            float gt = tanhf(gv[q] + bg);
            float os = 1.0f / (1.0f + expf(-(ov[q] + bo)));
            float cn = fs * creg[q] + is * gt;
            creg[q] = cn;
            float h = os * tanhf(cn);
            int b = b0 + q;
            uint32_t off = sw128((uint32_t)(b * 128 + col * 2)) >> 1;
            __nv_bfloat16 hh = __float2bfloat16(h);
            hout[kct * 8192 + off] = hh;
            hout[kct * 8192 + 4096 + off] = __float2bfloat16(h - __bfloat162float(hh));
            if (ISL1 && tstep == TLEN - 1) g_h1final[b * HID + hdim] = h;
        }
    }
}

__global__ void __launch_bounds__(NTHR, 1)
lstm_persistent_kernel()
{
    extern __shared__ __align__(1024) char smem[];
    uint32_t sbase = smem_u32(smem);
    const int tid = threadIdx.x;

    {   // zero h tile buffers (both parities)
        uint32_t* z0 = reinterpret_cast<uint32_t*>(&g_h0t[0][0][0]);
        uint32_t* z1 = reinterpret_cast<uint32_t*>(&g_h1t[0][0][0]);
        for (int i = blockIdx.x * NTHR + tid; i < 131072; i += NCTA * NTHR) {
            z0[i] = 0u; z1[i] = 0u;
        }
    }
    grid_barrier();

    const bool isl1 = blockIdx.x < 64;
    const int mt = isl1 ? blockIdx.x : blockIdx.x - 64;
    float creg[4] = {0.f, 0.f, 0.f, 0.f};

    if (!isl1)
        run_step<NCH0, false>(smem, sbase, mt, 0, creg);
    grid_barrier();

    for (int t = 0; t < TLEN; t++) {
        if (isl1)
            run_step<NCH1, true>(smem, sbase, mt, t, creg);
        else if (t + 1 < TLEN)
            run_step<NCH0, false>(smem, sbase, mt, t + 1, creg);
        grid_barrier();
    }
}

// ---------------- prep kernels (gate-permuted, swizzled, hi/lo split) -------
__device__ __forceinline__ void split_store(__nv_bfloat16* hp, __nv_bfloat16* lp, float w) {
    __nv_bfloat16 hi = __float2bfloat16(w);
    *hp = hi;
    *lp = __float2bfloat16(w - __bfloat162float(hi));
}

// combined W prep: blocks [0, 32768) -> W1, [32768, 51200) -> W0
__global__ void prep_w_kernel(const float* __restrict__ Wih1, const float* __restrict__ Whh1,
                              const float* __restrict__ Wih0, const float* __restrict__ Whh0) {
    if (blockIdx.x < 32768) {
        int idx = blockIdx.x * 256 + threadIdx.x;
        int c = idx & 63, r = (idx >> 6) & 127, kc = (idx >> 13) & 31, mm = idx >> 18;
        int orig = (r & 3) * 1024 + mm * 32 + (r >> 2);
        int kg = kc * 64 + c;
        float w = (kg < 1024) ? Wih1[orig * 1024 + kg] : Whh1[orig * 1024 + kg - 1024];
        int base = (mm * NCH1 + kc) * 16384;
        uint32_t off = sw128((uint32_t)(r * 128 + c * 2)) >> 1;
        split_store(&g_w1[base + off], &g_w1[base + 8192 + off], w);
    } else {
        int idx = (blockIdx.x - 32768) * 256 + threadIdx.x;
        int c = idx & 63, r = (idx >> 6) & 127;
        int rest = idx >> 13;
        int kc = rest % NCH0, mm = rest / NCH0;
        int orig = (r & 3) * 1024 + mm * 32 + (r >> 2);
        int kg = kc * 64 + c;
        float w = (kg < 128) ? Wih0[orig * 128 + kg] : Whh0[orig * 1024 + kg - 128];
        int base = (mm * NCH0 + kc) * 16384;
        uint32_t off = sw128((uint32_t)(r * 128 + c * 2)) >> 1;
        split_store(&g_w0[base + off], &g_w0[base + 8192 + off], w);
    }
}

__global__ void prep_x_kernel(const float* __restrict__ x) {
    int idx = blockIdx.x * 256 + threadIdx.x;            // 4194304
    int c = idx & 63, b = (idx >> 6) & 63, kc = (idx >> 12) & 1, t = idx >> 13;
    float v = x[b * (TLEN * 128) + t * 128 + kc * 64 + c];
    int base = (t * 2 + kc) * 8192;
    uint32_t off = sw128((uint32_t)(b * 128 + c * 2)) >> 1;
    split_store(&g_xt[base + off], &g_xt[base + 4096 + off], v);
}

__global__ void prep_bias_kernel(const float* __restrict__ bih0, const float* __restrict__ bhh0,
                                 const float* __restrict__ bih1, const float* __restrict__ bhh1) {
    int idx = blockIdx.x * 256 + threadIdx.x;            // 8192
    int l = idx >> 12, p = idx & 4095;
    int mm = p >> 7, r = p & 127;
    int orig = (r & 3) * 1024 + mm * 32 + (r >> 2);
    g_biasp[l][p] = l ? (bih1[orig] + bhh1[orig]) : (bih0[orig] + bhh0[orig]);
}

__global__ void lstm_fc_kernel(const float* __restrict__ h,
                               const float* __restrict__ w,
                               const float* __restrict__ bias,
                               float* __restrict__ out) {
    __shared__ float warpsum[8];
    int b = blockIdx.x, tid = threadIdx.x;
    float s = 0.0f;
    for (int mm = tid; mm < HID; mm += 256) s += h[b * HID + mm] * w[mm];
#pragma unroll
    for (int o = 16; o; o >>= 1) s += __shfl_down_sync(0xffffffffu, s, o);
    if ((tid & 31) == 0) warpsum[tid >> 5] = s;
    __syncthreads();
    if (tid == 0) {
        float t = 0.0f;
#pragma unroll
        for (int i = 0; i < 8; i++) t += warpsum[i];
        out[b] = t + bias[0];
    }
}

extern "C" void kernel_launch(void* const* d_in, const int* in_sizes, int n_in,
                              void* d_out, int out_size) {
    const float* x    = (const float*)d_in[0];
    const float* Wih0 = (const float*)d_in[1];
    const float* Whh0 = (const float*)d_in[2];
    const float* bih0 = (const float*)d_in[3];
    const float* bhh0 = (const float*)d_in[4];
    const float* Wih1 = (const float*)d_in[5];
    const float* Whh1 = (const float*)d_in[6];
    const float* bih1 = (const float*)d_in[7];
    const float* bhh1 = (const float*)d_in[8];
    const float* fcw  = (const float*)d_in[9];
    const float* fcb  = (const float*)d_in[10];
    float* out = (float*)d_out;

    cudaFuncSetAttribute(lstm_persistent_kernel,
                         cudaFuncAttributeMaxDynamicSharedMemorySize, SMEM_TOTAL);
    float* h1f;
    cudaGetSymbolAddress((void**)&h1f, g_h1final);

    // persistent kernel deliberately the 4th launch (ncu capture slot)
    prep_bias_kernel<<<32, 256>>>(bih0, bhh0, bih1, bhh1);
    prep_w_kernel<<<51200, 256>>>(Wih1, Whh1, Wih0, Whh0);
    prep_x_kernel<<<16384, 256>>>(x);
    lstm_persistent_kernel<<<NCTA, NTHR, SMEM_TOTAL>>>();
    lstm_fc_kernel<<<64, 256>>>(h1f, fcw, fcb, out);
}